// round 1
// baseline (speedup 1.0000x reference)
#include <cuda_runtime.h>
#include <math.h>

#define TT 256
#define DD 64
#define SS 64
#define VV 32

// shared layout (in floats)
#define OFF_W1    0        // 4096
#define OFF_B1    4096     // 64
#define OFF_W2    4160     // 64
#define OFF_MAP   4224     // 2048
#define OFF_STEP  6272     // 4096
#define OFF_X     10368    // 8 warps * 4 tok * 64 = 2048
#define OFF_LISTS 12416    // 512 ints
#define OFF_WALK  12928    // 64
#define OFF_NWALK 12992    // 64
#define OFF_ACCV  13056    // 32
#define OFF_ACCS  13088    // 64
#define OFF_GS    13152    // 128
#define OFF_H     13280    // 128
#define OFF_CNT   13408    // 2 ints
#define SMEM_FLOATS 13412

__device__ __forceinline__ float gelu_exact(float x) {
    return 0.5f * x * (1.0f + erff(x * 0.70710678118654752440f));
}

__device__ __forceinline__ void process_events(
    const int* __restrict__ list, int n, float b2, float* __restrict__ target,
    const float* __restrict__ sW1, const float* __restrict__ sb1,
    const float* __restrict__ sw2, const float* __restrict__ evb,
    float* __restrict__ sXw, int lane)
{
    const int wid = threadIdx.x >> 5;
    for (int base = wid * 4; base < n; base += 32) {
        int items[4], toks[4];
        bool valid[4];
#pragma unroll
        for (int i = 0; i < 4; i++) {
            int idx = base + i;
            valid[i] = (idx < n);
            int ci = valid[i] ? idx : (n - 1);
            items[i] = list[ci];
            toks[i]  = items[i] & 255;
        }
        // stage the 4 evidence rows into this warp's shared x buffer
#pragma unroll
        for (int i = 0; i < 4; i++) {
            float2 v = *(const float2*)(evb + toks[i] * DD + 2 * lane);
            *(float2*)(sXw + i * DD + 2 * lane) = v;
        }
        __syncwarp();

        float acc0[4], acc1[4];
        float bb0 = sb1[2 * lane], bb1 = sb1[2 * lane + 1];
#pragma unroll
        for (int i = 0; i < 4; i++) { acc0[i] = bb0; acc1[i] = bb1; }

#pragma unroll
        for (int k = 0; k < DD; k += 4) {
            float4 xv[4];
#pragma unroll
            for (int i = 0; i < 4; i++) xv[i] = *(const float4*)(sXw + i * DD + k);
#pragma unroll
            for (int kk = 0; kk < 4; kk++) {
                float2 w = *(const float2*)(sW1 + (k + kk) * DD + 2 * lane);
#pragma unroll
                for (int i = 0; i < 4; i++) {
                    float xk = (&xv[i].x)[kk];
                    acc0[i] = fmaf(xk, w.x, acc0[i]);
                    acc1[i] = fmaf(xk, w.y, acc1[i]);
                }
            }
        }

        float w2a = sw2[2 * lane], w2b = sw2[2 * lane + 1];
#pragma unroll
        for (int i = 0; i < 4; i++) {
            float p = gelu_exact(acc0[i]) * w2a + gelu_exact(acc1[i]) * w2b;
#pragma unroll
            for (int off = 16; off; off >>= 1)
                p += __shfl_xor_sync(0xffffffffu, p, off);
            if (lane == 0 && valid[i]) {
                float g = 1.0f / (1.0f + expf(-(p + b2)));
                atomicAdd(target + (items[i] >> 8), g);
            }
        }
        __syncwarp();
    }
}

__global__ __launch_bounds__(256, 1)
void cpm_kernel(
    const float* __restrict__ evidence,
    const int* __restrict__ marker,
    const int* __restrict__ src_idx,
    const int* __restrict__ src_valid,
    const int* __restrict__ tsym_idx,
    const int* __restrict__ tsym_valid,
    const int* __restrict__ tval_idx,
    const int* __restrict__ tval_valid,
    const int* __restrict__ query_idx,
    const int* __restrict__ query_valid,
    const float* __restrict__ symbol_emb,
    const float* __restrict__ value_emb,
    const float* __restrict__ mg_W1, const float* __restrict__ mg_b1,
    const float* __restrict__ mg_W2, const float* __restrict__ mg_b2,
    const float* __restrict__ sg_W1, const float* __restrict__ sg_b1,
    const float* __restrict__ sg_W2, const float* __restrict__ sg_b2,
    const float* __restrict__ sf_W1, const float* __restrict__ sf_b1,
    const float* __restrict__ sf_W2, const float* __restrict__ sf_b2,
    const float* __restrict__ oh_W1, const float* __restrict__ oh_b1,
    const float* __restrict__ oh_W2, const float* __restrict__ oh_b2,
    float* __restrict__ out, int B)
{
    extern __shared__ float sm[];
    float* sW1   = sm + OFF_W1;
    float* sb1   = sm + OFF_B1;
    float* sw2   = sm + OFF_W2;
    float* sMap  = sm + OFF_MAP;
    float* sStep = sm + OFF_STEP;
    float* sX    = sm + OFF_X;
    int*   sLmap = (int*)(sm + OFF_LISTS);
    int*   sLstep= sLmap + 256;
    float* sWalk = sm + OFF_WALK;
    float* sNwalk= sm + OFF_NWALK;
    float* sAccv = sm + OFF_ACCV;
    float* sAccs = sm + OFF_ACCS;
    float* sGs   = sm + OFF_GS;
    float* sH    = sm + OFF_H;
    int*   sCnt  = (int*)(sm + OFF_CNT);

    const int tid  = threadIdx.x;
    const int lane = tid & 31;
    const int wid  = tid >> 5;
    const int b    = blockIdx.x;

    if (tid < 2) sCnt[tid] = 0;
    __syncthreads();

    // zero per-batch memories (contiguous sMap+sStep region)
    for (int i = tid; i < 2048 + 4096; i += 256) sMap[i] = 0.f;

    // build compact event lists (thread t = token t, T == blockDim)
    {
        const int gt = b * TT + tid;
        int m  = marker[gt];
        int sv = src_valid[gt];
        if (sv != 0) {
            int si = src_idx[gt];
            si = min(max(si, 0), SS - 1);
            if (m == 1 || m == 2) {
                if (tval_valid[gt] != 0) {
                    int tv = tval_idx[gt];
                    tv = min(max(tv, 0), VV - 1);
                    int p = atomicAdd(&sCnt[0], 1);
                    sLmap[p] = tid | ((si * VV + tv) << 8);
                }
            } else if (m == 3) {
                if (tsym_valid[gt] != 0) {
                    int ts = tsym_idx[gt];
                    ts = min(max(ts, 0), SS - 1);
                    int p = atomicAdd(&sCnt[1], 1);
                    sLstep[p] = tid | ((si * SS + ts) << 8);
                }
            }
        }
    }

    // stage map-gain weights
    for (int i = tid; i < DD * DD; i += 256) sW1[i] = mg_W1[i];
    if (tid < DD) { sb1[tid] = mg_b1[tid]; sw2[tid] = mg_W2[tid]; }
    __syncthreads();

    const int nmap  = sCnt[0];
    const int nstep = sCnt[1];
    const float* evb = evidence + (size_t)b * TT * DD;
    float* sXw = sX + wid * 4 * DD;

    process_events(sLmap, nmap, mg_b2[0], sMap, sW1, sb1, sw2, evb, sXw, lane);
    __syncthreads();

    // stage step-gain weights (reuse buffer)
    for (int i = tid; i < DD * DD; i += 256) sW1[i] = sg_W1[i];
    if (tid < DD) { sb1[tid] = sg_b1[tid]; sw2[tid] = sg_W2[tid]; }
    __syncthreads();

    process_events(sLstep, nstep, sg_b2[0], sStep, sW1, sb1, sw2, evb, sXw, lane);
    __syncthreads();

    // ---- graph walk ----
    {
        int q = query_idx[b];
        q = min(max(q, 0), SS - 1);
        float qv = (float)query_valid[b];
        if (tid < SS) { sWalk[tid] = (tid == q) ? qv : 0.f; sAccs[tid] = 0.f; }
        if (tid < VV) sAccv[tid] = 0.f;
        __syncthreads();

        for (int it = 0; it < 4; ++it) {
            if (tid < SS) {
                float a = 0.f;
#pragma unroll 8
                for (int s = 0; s < SS; s++) a = fmaf(sWalk[s], symbol_emb[s * DD + tid], a);
                sAccs[tid] += a;
            } else if (tid < SS + VV) {
                int v = tid - SS;
                float a = 0.f;
#pragma unroll 8
                for (int s = 0; s < SS; s++) a = fmaf(sWalk[s], sMap[s * VV + v], a);
                sAccv[v] += a;
            } else if (tid < SS + VV + SS) {
                if (it < 3) {
                    int t2 = tid - SS - VV;
                    float a = 0.f;
#pragma unroll 8
                    for (int s = 0; s < SS; s++) a = fmaf(sWalk[s], sStep[s * SS + t2], a);
                    sNwalk[t2] = a;
                }
            }
            __syncthreads();
            if (it < 3 && tid < SS) sWalk[tid] = sNwalk[tid];
            __syncthreads();
        }

        // graph_state = [acc_symbols | acc_values @ value_emb]
        if (tid < DD) {
            float a = 0.f;
#pragma unroll
            for (int v = 0; v < VV; v++) a = fmaf(sAccv[v], value_emb[v * DD + tid], a);
            sGs[DD + tid] = a;
            sGs[tid] = sAccs[tid];
        }
        __syncthreads();

        // head hidden layers (oh for threads 0..63, sf for 64..127)
        if (tid < DD) {
            int j = tid;
            float a = oh_b1[j];
#pragma unroll 8
            for (int i = 0; i < 2 * DD; i++) a = fmaf(sGs[i], oh_W1[i * DD + j], a);
            sH[j] = gelu_exact(a);
        } else if (tid < 2 * DD) {
            int j = tid - DD;
            float a = sf_b1[j];
#pragma unroll 8
            for (int i = 0; i < 2 * DD; i++) a = fmaf(sGs[i], sf_W1[i * DD + j], a);
            sH[DD + j] = gelu_exact(a);
        }
        __syncthreads();

        // second layers + store: logits [B,32] then feedback [B,64]
        if (tid < VV) {
            int v = tid;
            float a = oh_b2[v];
#pragma unroll 8
            for (int j = 0; j < DD; j++) a = fmaf(sH[j], oh_W2[j * VV + v], a);
            out[(size_t)b * VV + v] = a;
        } else if (tid < VV + DD) {
            int d2 = tid - VV;
            float a = sf_b2[d2];
#pragma unroll 8
            for (int j = 0; j < DD; j++) a = fmaf(sH[DD + j], sf_W2[j * DD + d2], a);
            out[(size_t)B * VV + (size_t)b * DD + d2] = a;
        }
    }
}

extern "C" void kernel_launch(void* const* d_in, const int* in_sizes, int n_in,
                              void* d_out, int out_size)
{
    const float* evidence    = (const float*)d_in[0];
    const int*   marker      = (const int*)d_in[1];
    const int*   src_idx     = (const int*)d_in[2];
    const int*   src_valid   = (const int*)d_in[3];
    const int*   tsym_idx    = (const int*)d_in[4];
    const int*   tsym_valid  = (const int*)d_in[5];
    const int*   tval_idx    = (const int*)d_in[6];
    const int*   tval_valid  = (const int*)d_in[7];
    const int*   query_idx   = (const int*)d_in[8];
    const int*   query_valid = (const int*)d_in[9];
    const float* symbol_emb  = (const float*)d_in[10];
    const float* value_emb   = (const float*)d_in[11];
    const float* mg_W1 = (const float*)d_in[12];
    const float* mg_b1 = (const float*)d_in[13];
    const float* mg_W2 = (const float*)d_in[14];
    const float* mg_b2 = (const float*)d_in[15];
    const float* sg_W1 = (const float*)d_in[16];
    const float* sg_b1 = (const float*)d_in[17];
    const float* sg_W2 = (const float*)d_in[18];
    const float* sg_b2 = (const float*)d_in[19];
    const float* sf_W1 = (const float*)d_in[20];
    const float* sf_b1 = (const float*)d_in[21];
    const float* sf_W2 = (const float*)d_in[22];
    const float* sf_b2 = (const float*)d_in[23];
    const float* oh_W1 = (const float*)d_in[24];
    const float* oh_b1 = (const float*)d_in[25];
    const float* oh_W2 = (const float*)d_in[26];
    const float* oh_b2 = (const float*)d_in[27];

    const int B = in_sizes[8];  // query_idx has B elements
    const int smem_bytes = SMEM_FLOATS * (int)sizeof(float);

    cudaFuncSetAttribute(cpm_kernel, cudaFuncAttributeMaxDynamicSharedMemorySize, smem_bytes);

    cpm_kernel<<<B, 256, smem_bytes>>>(
        evidence, marker, src_idx, src_valid, tsym_idx, tsym_valid,
        tval_idx, tval_valid, query_idx, query_valid,
        symbol_emb, value_emb,
        mg_W1, mg_b1, mg_W2, mg_b2,
        sg_W1, sg_b1, sg_W2, sg_b2,
        sf_W1, sf_b1, sf_W2, sf_b2,
        oh_W1, oh_b1, oh_W2, oh_b2,
        (float*)d_out, B);
}

// round 2
// speedup vs baseline: 1.8249x; 1.8249x over previous
#include <cuda_runtime.h>
#include <math.h>

#define TT 256
#define DD 64
#define SS 64
#define VV 32

// shared layout (float slots), 2 batches per block
#define OFF_W1M   0        // 4096
#define OFF_W1S   4096     // 4096
#define OFF_B1M   8192     // 64
#define OFF_W2M   8256     // 64
#define OFF_B1S   8320     // 64
#define OFF_W2S   8384     // 64
#define OFF_LMAP  8448     // 2*256 ints
#define OFF_LSTEP 8960     // 2*256 ints
#define OFF_GMAP  9472     // 2*256
#define OFF_GSTEP 9984     // 2*256
#define OFF_X     10496    // 8 warps * 4 tok * 64 = 2048
#define OFF_WALK  12544    // 2*64
#define OFF_NW    12672    // 2*64
#define OFF_WSUM  12800    // 2*64
#define OFF_ACCV  12928    // 2*32
#define OFF_GS    12992    // 2*128
#define OFF_H     13248    // 2*128
#define OFF_CNT   13504    // 4 ints
#define SMEM_FLOATS 13508

__device__ __forceinline__ float gelu_exact(float x) {
    return 0.5f * x * (1.0f + erff(x * 0.70710678118654752440f));
}

// warp-cooperative gate MLP over a compacted event list; writes per-event gain
__device__ __forceinline__ void process_events(
    const int* __restrict__ list, int n, float b2,
    float* __restrict__ gout,
    const float* __restrict__ sW1, const float* __restrict__ sb1,
    const float* __restrict__ sw2, const float* __restrict__ evb,
    float* __restrict__ sXw, int lane)
{
    const int wid = threadIdx.x >> 5;
    for (int base = wid * 4; base < n; base += 32) {
        int items[4], toks[4];
        bool valid[4];
#pragma unroll
        for (int i = 0; i < 4; i++) {
            int idx = base + i;
            valid[i] = (idx < n);
            int ci = valid[i] ? idx : (n - 1);
            items[i] = list[ci];
            toks[i]  = items[i] & 255;
        }
#pragma unroll
        for (int i = 0; i < 4; i++) {
            float2 v = *(const float2*)(evb + toks[i] * DD + 2 * lane);
            *(float2*)(sXw + i * DD + 2 * lane) = v;
        }
        __syncwarp();

        float acc0[4], acc1[4];
        float bb0 = sb1[2 * lane], bb1 = sb1[2 * lane + 1];
#pragma unroll
        for (int i = 0; i < 4; i++) { acc0[i] = bb0; acc1[i] = bb1; }

#pragma unroll
        for (int k = 0; k < DD; k += 4) {
            float4 xv[4];
#pragma unroll
            for (int i = 0; i < 4; i++) xv[i] = *(const float4*)(sXw + i * DD + k);
#pragma unroll
            for (int kk = 0; kk < 4; kk++) {
                float2 w = *(const float2*)(sW1 + (k + kk) * DD + 2 * lane);
#pragma unroll
                for (int i = 0; i < 4; i++) {
                    float xk = (&xv[i].x)[kk];
                    acc0[i] = fmaf(xk, w.x, acc0[i]);
                    acc1[i] = fmaf(xk, w.y, acc1[i]);
                }
            }
        }

        float w2a = sw2[2 * lane], w2b = sw2[2 * lane + 1];
#pragma unroll
        for (int i = 0; i < 4; i++) {
            float p = gelu_exact(acc0[i]) * w2a + gelu_exact(acc1[i]) * w2b;
#pragma unroll
            for (int off = 16; off; off >>= 1)
                p += __shfl_xor_sync(0xffffffffu, p, off);
            if (lane == 0 && valid[i]) {
                gout[base + i] = 1.0f / (1.0f + expf(-(p + b2)));
            }
        }
        __syncwarp();
    }
}

__global__ __launch_bounds__(256, 3)
void cpm_kernel(
    const float* __restrict__ evidence,
    const int* __restrict__ marker,
    const int* __restrict__ src_idx,
    const int* __restrict__ src_valid,
    const int* __restrict__ tsym_idx,
    const int* __restrict__ tsym_valid,
    const int* __restrict__ tval_idx,
    const int* __restrict__ tval_valid,
    const int* __restrict__ query_idx,
    const int* __restrict__ query_valid,
    const float* __restrict__ symbol_emb,
    const float* __restrict__ value_emb,
    const float* __restrict__ mg_W1, const float* __restrict__ mg_b1,
    const float* __restrict__ mg_W2, const float* __restrict__ mg_b2,
    const float* __restrict__ sg_W1, const float* __restrict__ sg_b1,
    const float* __restrict__ sg_W2, const float* __restrict__ sg_b2,
    const float* __restrict__ sf_W1, const float* __restrict__ sf_b1,
    const float* __restrict__ sf_W2, const float* __restrict__ sf_b2,
    const float* __restrict__ oh_W1, const float* __restrict__ oh_b1,
    const float* __restrict__ oh_W2, const float* __restrict__ oh_b2,
    float* __restrict__ out, int B)
{
    extern __shared__ float sm[];
    float* sW1m  = sm + OFF_W1M;
    float* sW1s  = sm + OFF_W1S;
    float* sb1m  = sm + OFF_B1M;
    float* sw2m  = sm + OFF_W2M;
    float* sb1s  = sm + OFF_B1S;
    float* sw2s  = sm + OFF_W2S;
    int*   sLmap = (int*)(sm + OFF_LMAP);
    int*   sLstep= (int*)(sm + OFF_LSTEP);
    float* sGmap = sm + OFF_GMAP;
    float* sGstep= sm + OFF_GSTEP;
    float* sX    = sm + OFF_X;
    float* sWalk = sm + OFF_WALK;
    float* sNw   = sm + OFF_NW;
    float* sWsum = sm + OFF_WSUM;
    float* sAccv = sm + OFF_ACCV;
    float* sGs   = sm + OFF_GS;
    float* sH    = sm + OFF_H;
    int*   sCnt  = (int*)(sm + OFF_CNT);

    const int tid  = threadIdx.x;
    const int lane = tid & 31;
    const int wid  = tid >> 5;
    const int b0   = blockIdx.x * 2;

    if (tid < 4) sCnt[tid] = 0;
    __syncthreads();

    // build compact event lists for both batches (thread tid = token tid)
#pragma unroll
    for (int bi = 0; bi < 2; bi++) {
        const int b = b0 + bi;
        if (b >= B) break;
        const int gt = b * TT + tid;
        int m  = marker[gt];
        int sv = src_valid[gt];
        if (sv != 0) {
            int si = min(max(src_idx[gt], 0), SS - 1);
            if (m == 1 || m == 2) {
                if (tval_valid[gt] != 0) {
                    int tv = min(max(tval_idx[gt], 0), VV - 1);
                    int p = atomicAdd(&sCnt[bi * 2 + 0], 1);
                    sLmap[bi * 256 + p] = tid | (si << 8) | (tv << 14);
                }
            } else if (m == 3) {
                if (tsym_valid[gt] != 0) {
                    int ts = min(max(tsym_idx[gt], 0), SS - 1);
                    int p = atomicAdd(&sCnt[bi * 2 + 1], 1);
                    sLstep[bi * 256 + p] = tid | (si << 8) | (ts << 14);
                }
            }
        }
    }

    // stage both gate-MLP weight sets
    for (int i = tid; i < DD * DD; i += 256) { sW1m[i] = mg_W1[i]; sW1s[i] = sg_W1[i]; }
    if (tid < DD) {
        sb1m[tid] = mg_b1[tid]; sw2m[tid] = mg_W2[tid];
        sb1s[tid] = sg_b1[tid]; sw2s[tid] = sg_W2[tid];
    }
    __syncthreads();

    const float mgb2 = mg_b2[0];
    const float sgb2 = sg_b2[0];
    float* sXw = sX + wid * 4 * DD;

#pragma unroll
    for (int bi = 0; bi < 2; bi++) {
        const int b = b0 + bi;
        if (b >= B) break;
        const float* evb = evidence + (size_t)b * TT * DD;
        process_events(sLmap + bi * 256, sCnt[bi * 2 + 0], mgb2, sGmap + bi * 256,
                       sW1m, sb1m, sw2m, evb, sXw, lane);
        process_events(sLstep + bi * 256, sCnt[bi * 2 + 1], sgb2, sGstep + bi * 256,
                       sW1s, sb1s, sw2s, evb, sXw, lane);
    }
    __syncthreads();

    // ---- sparse walk: warp 0 -> batch 0, warp 1 -> batch 1 ----
    if (wid < 2) {
        const int bi = wid;
        const int b = b0 + bi;
        if (b < B) {
            float* walk = sWalk + bi * SS;
            float* nw   = sNw   + bi * SS;
            float* wsum = sWsum + bi * SS;
            float* accv = sAccv + bi * VV;
            const int* lmap  = sLmap  + bi * 256;
            const int* lstep = sLstep + bi * 256;
            const float* gmap  = sGmap  + bi * 256;
            const float* gstep = sGstep + bi * 256;
            const int nmap  = sCnt[bi * 2 + 0];
            const int nstep = sCnt[bi * 2 + 1];

            int q = min(max(query_idx[b], 0), SS - 1);
            float qv = (float)query_valid[b];
#pragma unroll
            for (int i = lane; i < SS; i += 32) {
                float w = (i == q) ? qv : 0.f;
                walk[i] = w; wsum[i] = w;
            }
            if (lane < VV) accv[lane] = 0.f;
            __syncwarp();

            for (int it = 0; it < 3; it++) {
#pragma unroll
                for (int i = lane; i < SS; i += 32) nw[i] = 0.f;
                __syncwarp();
                for (int e = lane; e < nstep; e += 32) {
                    int item = lstep[e];
                    int src = (item >> 8) & 63;
                    int tgt = (item >> 14) & 63;
                    atomicAdd(&nw[tgt], gstep[e] * walk[src]);
                }
                __syncwarp();
#pragma unroll
                for (int i = lane; i < SS; i += 32) {
                    float w = nw[i];
                    walk[i] = w; wsum[i] += w;
                }
                __syncwarp();
            }
            for (int e = lane; e < nmap; e += 32) {
                int item = lmap[e];
                int src = (item >> 8) & 63;
                int tv  = (item >> 14) & 63;
                atomicAdd(&accv[tv], gmap[e] * wsum[src]);
            }
        }
    }
    __syncthreads();

    // ---- graph_state + heads: threads [0,128) -> batch0, [128,256) -> batch1 ----
    {
        const int bi = tid >> 7;          // 0 or 1
        const int lt = tid & 127;
        const int b = b0 + bi;
        if (b < B) {
            const float* wsum = sWsum + bi * SS;
            const float* accv = sAccv + bi * VV;
            float* gs = sGs + bi * 128;
            float* h  = sH  + bi * 128;

            if (lt < DD) {
                float a = 0.f;
#pragma unroll 8
                for (int s = 0; s < SS; s++) a = fmaf(wsum[s], symbol_emb[s * DD + lt], a);
                gs[lt] = a;
            } else {
                int d = lt - DD;
                float a = 0.f;
#pragma unroll
                for (int v = 0; v < VV; v++) a = fmaf(accv[v], value_emb[v * DD + d], a);
                gs[DD + d] = a;
            }
            __syncthreads();

            if (lt < DD) {
                float a = oh_b1[lt];
#pragma unroll 8
                for (int i = 0; i < 2 * DD; i++) a = fmaf(gs[i], oh_W1[i * DD + lt], a);
                h[lt] = gelu_exact(a);
            } else {
                int j = lt - DD;
                float a = sf_b1[j];
#pragma unroll 8
                for (int i = 0; i < 2 * DD; i++) a = fmaf(gs[i], sf_W1[i * DD + j], a);
                h[DD + j] = gelu_exact(a);
            }
            __syncthreads();

            if (lt < VV) {
                float a = oh_b2[lt];
#pragma unroll 8
                for (int j = 0; j < DD; j++) a = fmaf(h[j], oh_W2[j * VV + lt], a);
                out[(size_t)b * VV + lt] = a;
            } else if (lt < VV + DD) {
                int d2 = lt - VV;
                float a = sf_b2[d2];
#pragma unroll 8
                for (int j = 0; j < DD; j++) a = fmaf(h[DD + j], sf_W2[j * DD + d2], a);
                out[(size_t)B * VV + (size_t)b * DD + d2] = a;
            }
        } else {
            __syncthreads();
            __syncthreads();
        }
    }
}

extern "C" void kernel_launch(void* const* d_in, const int* in_sizes, int n_in,
                              void* d_out, int out_size)
{
    const float* evidence    = (const float*)d_in[0];
    const int*   marker      = (const int*)d_in[1];
    const int*   src_idx     = (const int*)d_in[2];
    const int*   src_valid   = (const int*)d_in[3];
    const int*   tsym_idx    = (const int*)d_in[4];
    const int*   tsym_valid  = (const int*)d_in[5];
    const int*   tval_idx    = (const int*)d_in[6];
    const int*   tval_valid  = (const int*)d_in[7];
    const int*   query_idx   = (const int*)d_in[8];
    const int*   query_valid = (const int*)d_in[9];
    const float* symbol_emb  = (const float*)d_in[10];
    const float* value_emb   = (const float*)d_in[11];
    const float* mg_W1 = (const float*)d_in[12];
    const float* mg_b1 = (const float*)d_in[13];
    const float* mg_W2 = (const float*)d_in[14];
    const float* mg_b2 = (const float*)d_in[15];
    const float* sg_W1 = (const float*)d_in[16];
    const float* sg_b1 = (const float*)d_in[17];
    const float* sg_W2 = (const float*)d_in[18];
    const float* sg_b2 = (const float*)d_in[19];
    const float* sf_W1 = (const float*)d_in[20];
    const float* sf_b1 = (const float*)d_in[21];
    const float* sf_W2 = (const float*)d_in[22];
    const float* sf_b2 = (const float*)d_in[23];
    const float* oh_W1 = (const float*)d_in[24];
    const float* oh_b1 = (const float*)d_in[25];
    const float* oh_W2 = (const float*)d_in[26];
    const float* oh_b2 = (const float*)d_in[27];

    const int B = in_sizes[8];  // query_idx has B elements
    const int smem_bytes = SMEM_FLOATS * (int)sizeof(float);

    cudaFuncSetAttribute(cpm_kernel, cudaFuncAttributeMaxDynamicSharedMemorySize, smem_bytes);

    const int grid = (B + 1) / 2;
    cpm_kernel<<<grid, 256, smem_bytes>>>(
        evidence, marker, src_idx, src_valid, tsym_idx, tsym_valid,
        tval_idx, tval_valid, query_idx, query_valid,
        symbol_emb, value_emb,
        mg_W1, mg_b1, mg_W2, mg_b2,
        sg_W1, sg_b1, sg_W2, sg_b2,
        sf_W1, sf_b1, sf_W2, sf_b2,
        oh_W1, oh_b1, oh_W2, oh_b2,
        (float*)d_out, B);
}

// round 3
// speedup vs baseline: 2.0107x; 1.1018x over previous
#include <cuda_runtime.h>
#include <math.h>

#define TT 256
#define DD 64
#define SS 64
#define VV 32

typedef unsigned long long u64;

// shared layout (float slots), 2 batches per block, merged event lists
#define OFF_W1M   0        // 4096
#define OFF_W1S   4096     // 4096
#define OFF_B1M   8192     // 64
#define OFF_W2M   8256     // 64
#define OFF_B1S   8320     // 64
#define OFF_W2S   8384     // 64
#define OFF_LMAP  8448     // 512 ints (merged)
#define OFF_LSTEP 8960     // 512 ints (merged)
#define OFF_GMAP  9472     // 512
#define OFF_GSTEP 9984     // 512
#define OFF_X     10496    // 8 warps * 4 tok * 128 (duplicated) = 4096
#define OFF_WALK  14592    // 2*64
#define OFF_NW    14720    // 2*64
#define OFF_WSUM  14848    // 2*64
#define OFF_ACCV  14976    // 2*32
#define OFF_GS    15040    // 2*128
#define OFF_H     15296    // 2*128
#define OFF_CNT   15552    // 4 ints
#define SMEM_FLOATS 15556

__device__ __forceinline__ float gelu_exact(float x) {
    return 0.5f * x * (1.0f + erff(x * 0.70710678118654752440f));
}

__device__ __forceinline__ u64 ffma2(u64 a, u64 b, u64 c) {
    u64 d;
    asm("fma.rn.f32x2 %0, %1, %2, %3;" : "=l"(d) : "l"(a), "l"(b), "l"(c));
    return d;
}

// warp-cooperative gate MLP over a merged (2-batch) event list
// item encoding: tok[0:8) | bbit[8] | src[9:15) | tgt[15:21)
__device__ __forceinline__ void process_events(
    const int* __restrict__ list, int n, float b2,
    float* __restrict__ gout,
    const float* __restrict__ sW1, const float* __restrict__ sb1,
    const float* __restrict__ sw2,
    const float* __restrict__ evidence, int b0,
    float* __restrict__ sXw, int lane)
{
    const int wid = threadIdx.x >> 5;
    for (int base = wid * 4; base < n; base += 32) {
        int items[4];
        bool valid[4];
#pragma unroll
        for (int i = 0; i < 4; i++) {
            int idx = base + i;
            valid[i] = (idx < n);
            items[i] = list[valid[i] ? idx : (n - 1)];
        }
        // stage 4 evidence rows, duplicated: (x,x,y,y) per float2
#pragma unroll
        for (int i = 0; i < 4; i++) {
            int tok = items[i] & 255;
            int bb  = (items[i] >> 8) & 1;
            const float* ev = evidence + ((size_t)(b0 + bb) * TT + tok) * DD;
            float2 v = *(const float2*)(ev + 2 * lane);
            float4 d = make_float4(v.x, v.x, v.y, v.y);
            *(float4*)(sXw + i * 2 * DD + 4 * lane) = d;
        }
        __syncwarp();

        u64 acc[4];
        u64 bpair = *(const u64*)(sb1 + 2 * lane);
#pragma unroll
        for (int i = 0; i < 4; i++) acc[i] = bpair;

#pragma unroll
        for (int k = 0; k < DD; k += 2) {
            u64 w0 = *(const u64*)(sW1 + k * DD + 2 * lane);
            u64 w1 = *(const u64*)(sW1 + (k + 1) * DD + 2 * lane);
#pragma unroll
            for (int i = 0; i < 4; i++) {
                ulonglong2 xd = *(const ulonglong2*)(sXw + i * 2 * DD + 2 * k);
                acc[i] = ffma2(xd.x, w0, acc[i]);
                acc[i] = ffma2(xd.y, w1, acc[i]);
            }
        }

        float w2a = sw2[2 * lane], w2b = sw2[2 * lane + 1];
#pragma unroll
        for (int i = 0; i < 4; i++) {
            float lo, hi;
            asm("mov.b64 {%0,%1}, %2;" : "=f"(lo), "=f"(hi) : "l"(acc[i]));
            float p = gelu_exact(lo) * w2a + gelu_exact(hi) * w2b;
#pragma unroll
            for (int off = 16; off; off >>= 1)
                p += __shfl_xor_sync(0xffffffffu, p, off);
            if (lane == 0 && valid[i]) {
                gout[base + i] = 1.0f / (1.0f + expf(-(p + b2)));
            }
        }
        __syncwarp();
    }
}

__global__ __launch_bounds__(256, 3)
void cpm_kernel(
    const float* __restrict__ evidence,
    const int* __restrict__ marker,
    const int* __restrict__ src_idx,
    const int* __restrict__ src_valid,
    const int* __restrict__ tsym_idx,
    const int* __restrict__ tsym_valid,
    const int* __restrict__ tval_idx,
    const int* __restrict__ tval_valid,
    const int* __restrict__ query_idx,
    const int* __restrict__ query_valid,
    const float* __restrict__ symbol_emb,
    const float* __restrict__ value_emb,
    const float* __restrict__ mg_W1, const float* __restrict__ mg_b1,
    const float* __restrict__ mg_W2, const float* __restrict__ mg_b2,
    const float* __restrict__ sg_W1, const float* __restrict__ sg_b1,
    const float* __restrict__ sg_W2, const float* __restrict__ sg_b2,
    const float* __restrict__ sf_W1, const float* __restrict__ sf_b1,
    const float* __restrict__ sf_W2, const float* __restrict__ sf_b2,
    const float* __restrict__ oh_W1, const float* __restrict__ oh_b1,
    const float* __restrict__ oh_W2, const float* __restrict__ oh_b2,
    float* __restrict__ out, int B)
{
    extern __shared__ float sm[];
    float* sW1m  = sm + OFF_W1M;
    float* sW1s  = sm + OFF_W1S;
    float* sb1m  = sm + OFF_B1M;
    float* sw2m  = sm + OFF_W2M;
    float* sb1s  = sm + OFF_B1S;
    float* sw2s  = sm + OFF_W2S;
    int*   sLmap = (int*)(sm + OFF_LMAP);
    int*   sLstep= (int*)(sm + OFF_LSTEP);
    float* sGmap = sm + OFF_GMAP;
    float* sGstep= sm + OFF_GSTEP;
    float* sX    = sm + OFF_X;
    float* sWalk = sm + OFF_WALK;
    float* sNw   = sm + OFF_NW;
    float* sWsum = sm + OFF_WSUM;
    float* sAccv = sm + OFF_ACCV;
    float* sGs   = sm + OFF_GS;
    float* sH    = sm + OFF_H;
    int*   sCnt  = (int*)(sm + OFF_CNT);

    const int tid  = threadIdx.x;
    const int lane = tid & 31;
    const int wid  = tid >> 5;
    const int b0   = blockIdx.x * 2;

    if (tid < 4) sCnt[tid] = 0;
    __syncthreads();

    // build merged compact event lists for both batches
#pragma unroll
    for (int bi = 0; bi < 2; bi++) {
        const int b = b0 + bi;
        if (b >= B) break;
        const int gt = b * TT + tid;
        int m  = marker[gt];
        int sv = src_valid[gt];
        if (sv != 0) {
            int si = min(max(src_idx[gt], 0), SS - 1);
            if (m == 1 || m == 2) {
                if (tval_valid[gt] != 0) {
                    int tv = min(max(tval_idx[gt], 0), VV - 1);
                    int p = atomicAdd(&sCnt[0], 1);
                    sLmap[p] = tid | (bi << 8) | (si << 9) | (tv << 15);
                }
            } else if (m == 3) {
                if (tsym_valid[gt] != 0) {
                    int ts = min(max(tsym_idx[gt], 0), SS - 1);
                    int p = atomicAdd(&sCnt[1], 1);
                    sLstep[p] = tid | (bi << 8) | (si << 9) | (ts << 15);
                }
            }
        }
    }

    // stage both gate-MLP weight sets
    for (int i = tid; i < DD * DD; i += 256) { sW1m[i] = mg_W1[i]; sW1s[i] = sg_W1[i]; }
    if (tid < DD) {
        sb1m[tid] = mg_b1[tid]; sw2m[tid] = mg_W2[tid];
        sb1s[tid] = sg_b1[tid]; sw2s[tid] = sg_W2[tid];
    }
    __syncthreads();

    const int nmap  = sCnt[0];
    const int nstep = sCnt[1];
    float* sXw = sX + wid * 4 * 2 * DD;

    process_events(sLmap, nmap, mg_b2[0], sGmap, sW1m, sb1m, sw2m,
                   evidence, b0, sXw, lane);
    process_events(sLstep, nstep, sg_b2[0], sGstep, sW1s, sb1s, sw2s,
                   evidence, b0, sXw, lane);
    __syncthreads();

    // ---- sparse walk: warp 0 -> batch 0, warp 1 -> batch 1 ----
    if (wid < 2) {
        const int bi = wid;
        const int b = b0 + bi;
        if (b < B) {
            float* walk = sWalk + bi * SS;
            float* nw   = sNw   + bi * SS;
            float* wsum = sWsum + bi * SS;
            float* accv = sAccv + bi * VV;

            int q = min(max(query_idx[b], 0), SS - 1);
            float qv = (float)query_valid[b];
#pragma unroll
            for (int i = lane; i < SS; i += 32) {
                float w = (i == q) ? qv : 0.f;
                walk[i] = w; wsum[i] = w;
            }
            if (lane < VV) accv[lane] = 0.f;
            __syncwarp();

            for (int it = 0; it < 3; it++) {
#pragma unroll
                for (int i = lane; i < SS; i += 32) nw[i] = 0.f;
                __syncwarp();
                for (int e = lane; e < nstep; e += 32) {
                    int item = sLstep[e];
                    if (((item >> 8) & 1) == bi) {
                        int src = (item >> 9) & 63;
                        int tgt = (item >> 15) & 63;
                        atomicAdd(&nw[tgt], sGstep[e] * walk[src]);
                    }
                }
                __syncwarp();
#pragma unroll
                for (int i = lane; i < SS; i += 32) {
                    float w = nw[i];
                    walk[i] = w; wsum[i] += w;
                }
                __syncwarp();
            }
            for (int e = lane; e < nmap; e += 32) {
                int item = sLmap[e];
                if (((item >> 8) & 1) == bi) {
                    int src = (item >> 9) & 63;
                    int tv  = (item >> 15) & 63;
                    atomicAdd(&accv[tv], sGmap[e] * wsum[src]);
                }
            }
        }
    }
    __syncthreads();

    // ---- graph_state + heads: threads [0,128) -> batch0, [128,256) -> batch1 ----
    {
        const int bi = tid >> 7;
        const int lt = tid & 127;
        const int b = b0 + bi;
        if (b < B) {
            const float* wsum = sWsum + bi * SS;
            const float* accv = sAccv + bi * VV;
            float* gs = sGs + bi * 128;
            float* h  = sH  + bi * 128;

            if (lt < DD) {
                float a = 0.f;
#pragma unroll 8
                for (int s = 0; s < SS; s++) a = fmaf(wsum[s], symbol_emb[s * DD + lt], a);
                gs[lt] = a;
            } else {
                int d = lt - DD;
                float a = 0.f;
#pragma unroll
                for (int v = 0; v < VV; v++) a = fmaf(accv[v], value_emb[v * DD + d], a);
                gs[DD + d] = a;
            }
            __syncthreads();

            if (lt < DD) {
                float a = oh_b1[lt];
#pragma unroll 8
                for (int i = 0; i < 2 * DD; i++) a = fmaf(gs[i], oh_W1[i * DD + lt], a);
                h[lt] = gelu_exact(a);
            } else {
                int j = lt - DD;
                float a = sf_b1[j];
#pragma unroll 8
                for (int i = 0; i < 2 * DD; i++) a = fmaf(gs[i], sf_W1[i * DD + j], a);
                h[DD + j] = gelu_exact(a);
            }
            __syncthreads();

            if (lt < VV) {
                float a = oh_b2[lt];
#pragma unroll 8
                for (int j = 0; j < DD; j++) a = fmaf(h[j], oh_W2[j * VV + lt], a);
                out[(size_t)b * VV + lt] = a;
            } else if (lt < VV + DD) {
                int d2 = lt - VV;
                float a = sf_b2[d2];
#pragma unroll 8
                for (int j = 0; j < DD; j++) a = fmaf(h[DD + j], sf_W2[j * DD + d2], a);
                out[(size_t)B * VV + (size_t)b * DD + d2] = a;
            }
        } else {
            __syncthreads();
            __syncthreads();
        }
    }
}

extern "C" void kernel_launch(void* const* d_in, const int* in_sizes, int n_in,
                              void* d_out, int out_size)
{
    const float* evidence    = (const float*)d_in[0];
    const int*   marker      = (const int*)d_in[1];
    const int*   src_idx     = (const int*)d_in[2];
    const int*   src_valid   = (const int*)d_in[3];
    const int*   tsym_idx    = (const int*)d_in[4];
    const int*   tsym_valid  = (const int*)d_in[5];
    const int*   tval_idx    = (const int*)d_in[6];
    const int*   tval_valid  = (const int*)d_in[7];
    const int*   query_idx   = (const int*)d_in[8];
    const int*   query_valid = (const int*)d_in[9];
    const float* symbol_emb  = (const float*)d_in[10];
    const float* value_emb   = (const float*)d_in[11];
    const float* mg_W1 = (const float*)d_in[12];
    const float* mg_b1 = (const float*)d_in[13];
    const float* mg_W2 = (const float*)d_in[14];
    const float* mg_b2 = (const float*)d_in[15];
    const float* sg_W1 = (const float*)d_in[16];
    const float* sg_b1 = (const float*)d_in[17];
    const float* sg_W2 = (const float*)d_in[18];
    const float* sg_b2 = (const float*)d_in[19];
    const float* sf_W1 = (const float*)d_in[20];
    const float* sf_b1 = (const float*)d_in[21];
    const float* sf_W2 = (const float*)d_in[22];
    const float* sf_b2 = (const float*)d_in[23];
    const float* oh_W1 = (const float*)d_in[24];
    const float* oh_b1 = (const float*)d_in[25];
    const float* oh_W2 = (const float*)d_in[26];
    const float* oh_b2 = (const float*)d_in[27];

    const int B = in_sizes[8];
    const int smem_bytes = SMEM_FLOATS * (int)sizeof(float);

    cudaFuncSetAttribute(cpm_kernel, cudaFuncAttributeMaxDynamicSharedMemorySize, smem_bytes);

    const int grid = (B + 1) / 2;
    cpm_kernel<<<grid, 256, smem_bytes>>>(
        evidence, marker, src_idx, src_valid, tsym_idx, tsym_valid,
        tval_idx, tval_valid, query_idx, query_valid,
        symbol_emb, value_emb,
        mg_W1, mg_b1, mg_W2, mg_b2,
        sg_W1, sg_b1, sg_W2, sg_b2,
        sf_W1, sf_b1, sf_W2, sf_b2,
        oh_W1, oh_b1, oh_W2, oh_b2,
        (float*)d_out, B);
}